// round 1
// baseline (speedup 1.0000x reference)
#include <cuda_runtime.h>
#include <math.h>

#define Bb 4
#define Ll 4096
#define Dd 512
#define Hh 8
#define DK 64
#define Uu 45
#define SCALE 0.125f   // 1/sqrt(64)

// ---------------- scratch (device globals; no allocation allowed) ----------
__device__ float g_Qp[Bb*Ll*Dd];      // (B,L,H,dk) == row-major (B*L, D)
__device__ float g_Kp[Bb*Ll*Dd];
__device__ float g_Vp[Bb*Ll*Dd];
__device__ float g_ctx[Bb*Ll*Dd];     // (B,L,H,dk)
__device__ float g_M[Bb*Hh*Ll];
__device__ float g_vmean[Bb*Dd];      // (B, H*dk)
__device__ int   g_top[Bb*Hh*Uu];

// ---------------- 128x128x8 SGEMM with bias:  C = A(MxK) @ W(KxN) + b ------
#define BM 128
#define BN 128
#define BK 8
#define TM 8
#define TN 8

__global__ __launch_bounds__(256) void sgemm_bias(
    const float* __restrict__ A, const float* __restrict__ W,
    const float* __restrict__ bias, float* __restrict__ C,
    int M, int N, int K)
{
    __shared__ float As[BK][BM];
    __shared__ float Bs[BK][BN];
    const int tid  = threadIdx.x;
    const int brow = blockIdx.y, bcol = blockIdx.x;
    const int tcol = tid % (BN / TN);   // 0..15
    const int trow = tid / (BN / TN);   // 0..15

    float acc[TM][TN];
#pragma unroll
    for (int i = 0; i < TM; i++)
#pragma unroll
        for (int j = 0; j < TN; j++) acc[i][j] = 0.f;

    const int aRow = tid >> 1;             // 0..127
    const int aCol = (tid & 1) * 4;        // 0 or 4
    const int bRow = tid >> 5;             // 0..7
    const int bCol = (tid & 31) * 4;       // 0..124

    const float* Aptr = A + (size_t)(brow * BM) * K;
    const float* Wptr = W + bcol * BN;

    for (int k0 = 0; k0 < K; k0 += BK) {
        float4 a4 = *(const float4*)(Aptr + (size_t)aRow * K + k0 + aCol);
        As[aCol + 0][aRow] = a4.x;
        As[aCol + 1][aRow] = a4.y;
        As[aCol + 2][aRow] = a4.z;
        As[aCol + 3][aRow] = a4.w;
        float4 b4 = *(const float4*)(Wptr + (size_t)(k0 + bRow) * N + bCol);
        *(float4*)&Bs[bRow][bCol] = b4;
        __syncthreads();
#pragma unroll
        for (int kk = 0; kk < BK; kk++) {
            float ar[TM], br[TN];
#pragma unroll
            for (int i = 0; i < TM; i++) ar[i] = As[kk][trow * TM + i];
#pragma unroll
            for (int j = 0; j < TN; j++) br[j] = Bs[kk][tcol * TN + j];
#pragma unroll
            for (int i = 0; i < TM; i++)
#pragma unroll
                for (int j = 0; j < TN; j++) acc[i][j] += ar[i] * br[j];
        }
        __syncthreads();
    }

#pragma unroll
    for (int i = 0; i < TM; i++) {
        int r = brow * BM + trow * TM + i;
#pragma unroll
        for (int j = 0; j < TN; j += 4) {
            int c = bcol * BN + tcol * TN + j;
            float4 o;
            o.x = acc[i][j + 0] + bias[c + 0];
            o.y = acc[i][j + 1] + bias[c + 1];
            o.z = acc[i][j + 2] + bias[c + 2];
            o.w = acc[i][j + 3] + bias[c + 3];
            *(float4*)(C + (size_t)r * N + c) = o;
        }
    }
}

// ---------------- V mean over L per (b,h) ----------------------------------
__global__ __launch_bounds__(256) void vmean_kernel()
{
    int b = blockIdx.y, h = blockIdx.x;
    int tid = threadIdx.x;
    int d = tid & 63, part = tid >> 6;
    float s = 0.f;
    for (int k = part; k < Ll; k += 4)
        s += g_Vp[((size_t)(b * Ll + k) * Hh + h) * DK + d];
    __shared__ float sm[4][DK];
    sm[part][d] = s;
    __syncthreads();
    if (part == 0) {
        float t = sm[0][d] + sm[1][d] + sm[2][d] + sm[3][d];
        g_vmean[b * Dd + h * DK + d] = t * (1.0f / Ll);
    }
}

// ---------------- ctx <- broadcast vmean -----------------------------------
__global__ __launch_bounds__(256) void fill_ctx()
{
    int i = blockIdx.x * 256 + threadIdx.x;     // i < B*L*D, divisible
    int b = i / (Ll * Dd);
    int c = i % Dd;
    g_ctx[i] = g_vmean[b * Dd + c];
}

// ---------------- sparse metric M = max - mean over sampled keys -----------
__global__ __launch_bounds__(256) void metric_kernel(const int* __restrict__ sample_idx)
{
    int b = blockIdx.z, h = blockIdx.y;
    int l = blockIdx.x * 256 + threadIdx.x;
    __shared__ float Ks[Uu * DK];
    for (int i = threadIdx.x; i < Uu * DK; i += 256) {
        int j = i / DK, d = i % DK;
        int ksl = sample_idx[j];
        Ks[i] = g_Kp[((size_t)(b * Ll + ksl) * Hh + h) * DK + d];
    }
    __syncthreads();
    float q[DK];
    const float* qp = &g_Qp[((size_t)(b * Ll + l) * Hh + h) * DK];
#pragma unroll
    for (int d = 0; d < DK; d += 4) {
        float4 v = *(const float4*)(qp + d);
        q[d] = v.x; q[d + 1] = v.y; q[d + 2] = v.z; q[d + 3] = v.w;
    }
    float mx = -1e30f, sum = 0.f;
    for (int j = 0; j < Uu; j++) {
        float acc = 0.f;
#pragma unroll
        for (int d = 0; d < DK; d++) acc += q[d] * Ks[j * DK + d];
        mx = fmaxf(mx, acc);
        sum += acc;
    }
    g_M[(b * Hh + h) * Ll + l] = mx - sum * (1.0f / Uu);
}

// ---------------- iterative top-45 per (b,h): descending, tie->lower idx ---
__global__ __launch_bounds__(256) void topk_kernel()
{
    int bh = blockIdx.x;
    int tid = threadIdx.x;
    __shared__ float m[Ll];          // 16 KB
    __shared__ float sval[256];
    __shared__ int   sidx[256];
    for (int k = tid; k < Ll; k += 256) m[k] = g_M[bh * Ll + k];
    __syncthreads();
    for (int it = 0; it < Uu; it++) {
        float bv = -1e38f; int bi = Ll;
        for (int k = tid; k < Ll; k += 256) {
            float v = m[k];
            if (v > bv) { bv = v; bi = k; }     // strict > keeps smallest k
        }
        sval[tid] = bv; sidx[tid] = bi;
        __syncthreads();
        for (int s = 128; s > 0; s >>= 1) {
            if (tid < s) {
                float v2 = sval[tid + s]; int i2 = sidx[tid + s];
                if (v2 > sval[tid] || (v2 == sval[tid] && i2 < sidx[tid])) {
                    sval[tid] = v2; sidx[tid] = i2;
                }
            }
            __syncthreads();
        }
        if (tid == 0) { g_top[bh * Uu + it] = sidx[0]; m[sidx[0]] = -1e38f; }
        __syncthreads();
    }
}

// ---------------- per selected query: scores, softmax, attn out, ctx scatter
__global__ __launch_bounds__(256) void attn_kernel(float* __restrict__ attn_out)
{
    int b = blockIdx.z, h = blockIdx.y, u = blockIdx.x;
    int tid = threadIdx.x;
    __shared__ float qsh[DK];
    __shared__ float s[Ll];          // 16 KB
    __shared__ float red[256];
    __shared__ float part_acc[4][DK];

    int lsel = g_top[(b * Hh + h) * Uu + u];
    if (tid < DK) qsh[tid] = g_Qp[((size_t)(b * Ll + lsel) * Hh + h) * DK + tid];
    __syncthreads();

    float q[DK];
#pragma unroll
    for (int d = 0; d < DK; d++) q[d] = qsh[d];

    float lmax = -1e30f;
    for (int k = tid; k < Ll; k += 256) {
        const float* kp = &g_Kp[((size_t)(b * Ll + k) * Hh + h) * DK];
        float acc = 0.f;
#pragma unroll
        for (int d = 0; d < DK; d += 4) {
            float4 kv = *(const float4*)(kp + d);
            acc += q[d] * kv.x + q[d + 1] * kv.y + q[d + 2] * kv.z + q[d + 3] * kv.w;
        }
        acc *= SCALE;
        s[k] = acc;
        lmax = fmaxf(lmax, acc);
    }
    red[tid] = lmax;
    __syncthreads();
    for (int st = 128; st > 0; st >>= 1) {
        if (tid < st) red[tid] = fmaxf(red[tid], red[tid + st]);
        __syncthreads();
    }
    float mval = red[0];
    __syncthreads();

    float lsum = 0.f;
    for (int k = tid; k < Ll; k += 256) {
        float e = expf(s[k] - mval);
        s[k] = e;
        lsum += e;
    }
    red[tid] = lsum;
    __syncthreads();
    for (int st = 128; st > 0; st >>= 1) {
        if (tid < st) red[tid] += red[tid + st];
        __syncthreads();
    }
    float inv = 1.0f / red[0];
    __syncthreads();

    float* ap = attn_out + ((size_t)((b * Hh + h) * Uu + u)) * Ll;
    for (int k = tid; k < Ll; k += 256) ap[k] = s[k] * inv;

    // ctx_new[d] = sum_k attn[k] * V[b,h,k,d]
    int d = tid & 63, part = tid >> 6;
    float acc = 0.f;
    for (int k = part; k < Ll; k += 4)
        acc += s[k] * g_Vp[((size_t)(b * Ll + k) * Hh + h) * DK + d];
    part_acc[part][d] = acc;
    __syncthreads();
    if (part == 0) {
        float t = (part_acc[0][d] + part_acc[1][d] + part_acc[2][d] + part_acc[3][d]) * inv;
        g_ctx[((size_t)(b * Ll + lsel) * Hh + h) * DK + d] = t;
    }
}

// ---------------- launch ----------------------------------------------------
extern "C" void kernel_launch(void* const* d_in, const int* in_sizes, int n_in,
                              void* d_out, int out_size)
{
    const float* queries = (const float*)d_in[0];
    const float* keys    = (const float*)d_in[1];
    const float* values  = (const float*)d_in[2];
    const int*   sample  = (const int*)d_in[3];
    const float* Wq = (const float*)d_in[4];  const float* bq = (const float*)d_in[5];
    const float* Wk = (const float*)d_in[6];  const float* bk = (const float*)d_in[7];
    const float* Wv = (const float*)d_in[8];  const float* bv = (const float*)d_in[9];
    const float* Wo = (const float*)d_in[10]; const float* bo = (const float*)d_in[11];

    float* out      = (float*)d_out;
    float* attn_out = out + (size_t)Bb * Ll * Dd;

    float *Qp, *Kp, *Vp, *ctx;
    cudaGetSymbolAddress((void**)&Qp,  g_Qp);
    cudaGetSymbolAddress((void**)&Kp,  g_Kp);
    cudaGetSymbolAddress((void**)&Vp,  g_Vp);
    cudaGetSymbolAddress((void**)&ctx, g_ctx);

    dim3 gg(Dd / BN, (Bb * Ll) / BM);
    sgemm_bias<<<gg, 256>>>(queries, Wq, bq, Qp, Bb * Ll, Dd, Dd);
    sgemm_bias<<<gg, 256>>>(keys,    Wk, bk, Kp, Bb * Ll, Dd, Dd);
    sgemm_bias<<<gg, 256>>>(values,  Wv, bv, Vp, Bb * Ll, Dd, Dd);

    vmean_kernel<<<dim3(Hh, Bb), 256>>>();
    fill_ctx<<<(Bb * Ll * Dd) / 256, 256>>>();

    metric_kernel<<<dim3(Ll / 256, Hh, Bb), 256>>>(sample);
    topk_kernel<<<Bb * Hh, 256>>>();
    attn_kernel<<<dim3(Uu, Hh, Bb), 256>>>(attn_out);

    sgemm_bias<<<gg, 256>>>(ctx, Wo, bo, out, Bb * Ll, Dd, Dd);
}

// round 6
// speedup vs baseline: 1.2237x; 1.2237x over previous
#include <cuda_runtime.h>
#include <cuda_bf16.h>
#include <cstdint>
#include <math.h>

#define Bb 4
#define Ll 4096
#define Dd 512
#define Hh 8
#define DK 64
#define Uu 45
#define SCALE 0.125f
#define MM 16384
#define MK 8388608
#define WSZ 262144

// ---------------- PTX helpers (plain-sm_103-legal) ---------------------------
__device__ __forceinline__ uint32_t smem_u32(const void* p) {
    uint32_t a;
    asm("{ .reg .u64 t; cvta.to.shared.u64 t, %1; cvt.u32.u64 %0, t; }" : "=r"(a) : "l"(p));
    return a;
}
#define CP_ASYNC16(dst, src) \
    asm volatile("cp.async.cg.shared.global [%0], [%1], 16;" :: "r"(dst), "l"(src))
#define CP_COMMIT() asm volatile("cp.async.commit_group;" ::: "memory")
#define CP_WAIT1()  asm volatile("cp.async.wait_group 1;" ::: "memory")
#define CP_WAIT0()  asm volatile("cp.async.wait_group 0;" ::: "memory")

__device__ __forceinline__ void ldsm_x4(uint32_t* r, uint32_t addr) {
    asm volatile("ldmatrix.sync.aligned.m8n8.x4.shared.b16 {%0,%1,%2,%3}, [%4];"
        : "=r"(r[0]), "=r"(r[1]), "=r"(r[2]), "=r"(r[3]) : "r"(addr));
}
__device__ __forceinline__ void mma_bf16(float* d, const uint32_t* a, uint32_t b0, uint32_t b1) {
    asm volatile("mma.sync.aligned.m16n8k16.row.col.f32.bf16.bf16.f32 "
        "{%0,%1,%2,%3}, {%4,%5,%6,%7}, {%8,%9}, {%0,%1,%2,%3};"
        : "+f"(d[0]), "+f"(d[1]), "+f"(d[2]), "+f"(d[3])
        : "r"(a[0]), "r"(a[1]), "r"(a[2]), "r"(a[3]), "r"(b0), "r"(b1));
}

// ---------------- scratch ----------------------------------------------------
__device__ __nv_bfloat16 g_XH[3 * MK];     // level 0 (hi) of q|k|v
__device__ __nv_bfloat16 g_XL[3 * MK];     // level 1 (mid)
__device__ __nv_bfloat16 g_X2[3 * MK];     // level 2 (lo); later reused for ctx lvl2
__device__ __nv_bfloat16 g_WtH[4 * WSZ];
__device__ __nv_bfloat16 g_WtL[4 * WSZ];
__device__ __nv_bfloat16 g_Wt2[4 * WSZ];
__device__ float g_P[3 * MK];              // Qp | Kp | Vp, (B,L,H,dk)
__device__ float g_ctx[MK];
__device__ __nv_bfloat16 g_ctxH[MK];
__device__ __nv_bfloat16 g_ctxL[MK];
__device__ float g_M[Bb * Hh * Ll];
__device__ float g_vpart[32 * 8 * 64];
__device__ float g_vmean[Bb * Dd];
__device__ int   g_top[Bb * Hh * Uu];

// ---------------- 3-level split conversion -----------------------------------
__global__ __launch_bounds__(256) void conv_split3(const float* __restrict__ x,
                                                   __nv_bfloat16* __restrict__ h,
                                                   __nv_bfloat16* __restrict__ m,
                                                   __nv_bfloat16* __restrict__ l, int n4)
{
    int i = blockIdx.x * 256 + threadIdx.x;
    if (i >= n4) return;
    float4 v = ((const float4*)x)[i];
    float vv[4] = {v.x, v.y, v.z, v.w};
    __nv_bfloat16 hh[4], mm[4], ll[4];
#pragma unroll
    for (int j = 0; j < 4; j++) {
        hh[j] = __float2bfloat16(vv[j]);
        float r1 = vv[j] - __bfloat162float(hh[j]);
        mm[j] = __float2bfloat16(r1);
        ll[j] = __float2bfloat16(r1 - __bfloat162float(mm[j]));
    }
    ((__nv_bfloat162*)h)[2 * i + 0] = __halves2bfloat162(hh[0], hh[1]);
    ((__nv_bfloat162*)h)[2 * i + 1] = __halves2bfloat162(hh[2], hh[3]);
    ((__nv_bfloat162*)m)[2 * i + 0] = __halves2bfloat162(mm[0], mm[1]);
    ((__nv_bfloat162*)m)[2 * i + 1] = __halves2bfloat162(mm[2], mm[3]);
    ((__nv_bfloat162*)l)[2 * i + 0] = __halves2bfloat162(ll[0], ll[1]);
    ((__nv_bfloat162*)l)[2 * i + 1] = __halves2bfloat162(ll[2], ll[3]);
}

// transpose W[k][n] -> Wt[n][k], 3-level split
__global__ void conv_w3(const float* __restrict__ W,
                        __nv_bfloat16* __restrict__ WtH,
                        __nv_bfloat16* __restrict__ WtL,
                        __nv_bfloat16* __restrict__ Wt2)
{
    __shared__ float t[32][33];
    int n0 = blockIdx.x * 32, k0 = blockIdx.y * 32;
    int tx = threadIdx.x, ty = threadIdx.y;
#pragma unroll
    for (int i = 0; i < 4; i++)
        t[ty + i * 8][tx] = W[(size_t)(k0 + ty + i * 8) * 512 + n0 + tx];
    __syncthreads();
#pragma unroll
    for (int i = 0; i < 4; i++) {
        int n = n0 + ty + i * 8;
        float v = t[tx][ty + i * 8];
        __nv_bfloat16 hb = __float2bfloat16(v);
        float r1 = v - __bfloat162float(hb);
        __nv_bfloat16 mb = __float2bfloat16(r1);
        WtH[(size_t)n * 512 + k0 + tx] = hb;
        WtL[(size_t)n * 512 + k0 + tx] = mb;
        Wt2[(size_t)n * 512 + k0 + tx] = __float2bfloat16(r1 - __bfloat162float(mb));
    }
}

// ---------------- bf16 HMMA GEMM with 3- or 6-term split + bias --------------
// CTA tile 128x128x32, 8 warps of 64x32, cp.async double buffer.
// term tables: first 3 = verified 3-term set {hh, h*b1, a1*h}; 6 adds {h*b2, a2*h, a1*b1}
__device__ __constant__ int c_tA[6] = {0, 0, 1, 0, 2, 1};
__device__ __constant__ int c_tB[6] = {0, 1, 0, 2, 0, 1};
#define LDAB 40

__global__ __launch_bounds__(256) void gemm_hmma(
    const __nv_bfloat16* __restrict__ A0, const __nv_bfloat16* __restrict__ A1,
    const __nv_bfloat16* __restrict__ A2,
    const __nv_bfloat16* __restrict__ B0, const __nv_bfloat16* __restrict__ B1,
    const __nv_bfloat16* __restrict__ B2,
    const float* __restrict__ bi0, const float* __restrict__ bi1, const float* __restrict__ bi2,
    float* __restrict__ Cout, int mode)   // mode 0: QKV (z<2: 6 terms, z==2: 3), mode 1: 3 terms
{
    __shared__ __nv_bfloat16 As[2][128 * LDAB];
    __shared__ __nv_bfloat16 Bs[2][128 * LDAB];
    const int tid = threadIdx.x;
    const int w = tid >> 5, lane = tid & 31;
    const int z = blockIdx.z;
    const int m0 = blockIdx.x * 128, n0 = blockIdx.y * 128;
    const int nt = mode ? 3 : (z == 2 ? 3 : 6);
    const int NCH = nt * 16;

    const __nv_bfloat16* Alev[3] = {A0 + (size_t)z * MK, A1 + (size_t)z * MK, A2 + (size_t)z * MK};
    const __nv_bfloat16* Blev[3] = {B0 + (size_t)z * WSZ, B1 + (size_t)z * WSZ, B2 + (size_t)z * WSZ};

    const int m_off = (w >> 2) * 64, n_off = (w & 3) * 32;
    const int mi = lane >> 3, r8 = lane & 7;

    float acc[4][4][4];
#pragma unroll
    for (int i = 0; i < 4; i++)
#pragma unroll
        for (int j = 0; j < 4; j++)
#pragma unroll
            for (int q = 0; q < 4; q++) acc[i][j][q] = 0.f;

    const uint32_t sA0 = smem_u32(&As[0][0]);
    const uint32_t sB0 = smem_u32(&Bs[0][0]);
    const int lrow = tid >> 2;
    const int lcg  = (tid & 3) * 8;

    auto load_chunk = [&](int c, int buf) {
        int t = c >> 4, k0 = (c & 15) * 32;
        const __nv_bfloat16* Asrc = Alev[c_tA[t]];
        const __nv_bfloat16* Bsrc = Blev[c_tB[t]];
#pragma unroll
        for (int i = 0; i < 2; i++) {
            int row = lrow + i * 64;
            uint32_t da = sA0 + buf * (128 * LDAB * 2) + (row * LDAB + lcg) * 2;
            CP_ASYNC16(da, Asrc + (size_t)(m0 + row) * 512 + k0 + lcg);
            uint32_t db = sB0 + buf * (128 * LDAB * 2) + (row * LDAB + lcg) * 2;
            CP_ASYNC16(db, Bsrc + (size_t)(n0 + row) * 512 + k0 + lcg);
        }
    };

    load_chunk(0, 0);
    CP_COMMIT();

    for (int c = 0; c < NCH; c++) {
        int buf = c & 1;
        if (c + 1 < NCH) { load_chunk(c + 1, buf ^ 1); CP_COMMIT(); CP_WAIT1(); }
        else CP_WAIT0();
        __syncthreads();

        uint32_t sA = sA0 + buf * (128 * LDAB * 2);
        uint32_t sB = sB0 + buf * (128 * LDAB * 2);
#pragma unroll
        for (int kk = 0; kk < 2; kk++) {
            uint32_t a[4][4], b[2][4];
#pragma unroll
            for (int i = 0; i < 4; i++)
                ldsm_x4(a[i], sA + (uint32_t)(m_off + i * 16 + ((mi & 1) << 3) + r8) * 80
                              + kk * 32 + ((mi >> 1) << 4));
#pragma unroll
            for (int jg = 0; jg < 2; jg++)
                ldsm_x4(b[jg], sB + (uint32_t)(n_off + jg * 16 + ((mi >> 1) << 3) + r8) * 80
                               + kk * 32 + ((mi & 1) << 4));
#pragma unroll
            for (int i = 0; i < 4; i++)
#pragma unroll
                for (int j = 0; j < 4; j++)
                    mma_bf16(acc[i][j], a[i], b[j >> 1][(j & 1) * 2], b[j >> 1][(j & 1) * 2 + 1]);
        }
        __syncthreads();
    }

    const float* bs = (z == 0) ? bi0 : (z == 1) ? bi1 : bi2;
    float* Cz = Cout + (size_t)z * MK;
#pragma unroll
    for (int i = 0; i < 4; i++) {
        int row0 = m0 + m_off + i * 16 + (lane >> 2);
#pragma unroll
        for (int j = 0; j < 4; j++) {
            int col = n0 + n_off + j * 8 + (lane & 3) * 2;
            float bx = bs[col], by = bs[col + 1];
            float2 v0 = make_float2(acc[i][j][0] + bx, acc[i][j][1] + by);
            float2 v1 = make_float2(acc[i][j][2] + bx, acc[i][j][3] + by);
            *(float2*)(Cz + (size_t)row0 * 512 + col) = v0;
            *(float2*)(Cz + (size_t)(row0 + 8) * 512 + col) = v1;
        }
    }
}

// ---------------- V mean (two-stage) ----------------------------------------
__global__ __launch_bounds__(256) void vmean1(const float* __restrict__ Vp, float* __restrict__ vpart)
{
    int h = blockIdx.x, b = blockIdx.y, p = blockIdx.z;
    int d = threadIdx.x & 63, sub = threadIdx.x >> 6;
    float s = 0.f;
    for (int k = p * 512 + sub; k < (p + 1) * 512; k += 4)
        s += Vp[((size_t)(b * Ll + k) * Hh + h) * DK + d];
    __shared__ float smm[4][64];
    smm[sub][d] = s;
    __syncthreads();
    if (sub == 0)
        vpart[((size_t)((b * Hh + h) * 8 + p)) * 64 + d] = smm[0][d] + smm[1][d] + smm[2][d] + smm[3][d];
}

__global__ void vmean2(const float* __restrict__ vpart, float* __restrict__ vmean)
{
    int bh = blockIdx.x, d = threadIdx.x;
    float s = 0.f;
    for (int p = 0; p < 8; p++) s += vpart[(bh * 8 + p) * 64 + d];
    vmean[(bh >> 3) * Dd + (bh & 7) * DK + d] = s * (1.0f / Ll);
}

__global__ __launch_bounds__(256) void fill_ctx(const float* __restrict__ vmean, float* __restrict__ ctx)
{
    int i = blockIdx.x * 256 + threadIdx.x;
    int b = i / (Ll * Dd);
    int c = i % Dd;
    ctx[i] = vmean[b * Dd + c];
}

// ---------------- sparse metric ----------------------------------------------
__global__ __launch_bounds__(256) void metric_kernel(const float* __restrict__ Qp,
                                                     const float* __restrict__ Kp,
                                                     const int* __restrict__ sample_idx,
                                                     float* __restrict__ Mout)
{
    int b = blockIdx.z, h = blockIdx.y;
    int l = blockIdx.x * 256 + threadIdx.x;
    __shared__ float Ks[Uu * DK];
    for (int i = threadIdx.x; i < Uu * DK; i += 256) {
        int j = i / DK, d = i % DK;
        int ksl = sample_idx[j];
        Ks[i] = Kp[((size_t)(b * Ll + ksl) * Hh + h) * DK + d];
    }
    __syncthreads();
    float q[DK];
    const float* qp = &Qp[((size_t)(b * Ll + l) * Hh + h) * DK];
#pragma unroll
    for (int d = 0; d < DK; d += 4) {
        float4 v = *(const float4*)(qp + d);
        q[d] = v.x; q[d + 1] = v.y; q[d + 2] = v.z; q[d + 3] = v.w;
    }
    float mx = -1e30f, sum = 0.f;
    for (int j = 0; j < Uu; j++) {
        float acc = 0.f;
#pragma unroll
        for (int d = 0; d < DK; d++) acc += q[d] * Ks[j * DK + d];
        mx = fmaxf(mx, acc);
        sum += acc;
    }
    Mout[(b * Hh + h) * Ll + l] = mx - sum * (1.0f / Uu);
}

// ---------------- top-45 ------------------------------------------------------
__global__ __launch_bounds__(256) void topk_kernel(const float* __restrict__ Min, int* __restrict__ top)
{
    int bh = blockIdx.x;
    int tid = threadIdx.x;
    __shared__ float m[Ll];
    __shared__ float sval[256];
    __shared__ int   sidx[256];
    for (int k = tid; k < Ll; k += 256) m[k] = Min[bh * Ll + k];
    __syncthreads();
    for (int it = 0; it < Uu; it++) {
        float bv = -1e38f; int bi = Ll;
        for (int k = tid; k < Ll; k += 256) {
            float v = m[k];
            if (v > bv) { bv = v; bi = k; }
        }
        sval[tid] = bv; sidx[tid] = bi;
        __syncthreads();
        for (int s = 128; s > 0; s >>= 1) {
            if (tid < s) {
                float v2 = sval[tid + s]; int i2 = sidx[tid + s];
                if (v2 > sval[tid] || (v2 == sval[tid] && i2 < sidx[tid])) {
                    sval[tid] = v2; sidx[tid] = i2;
                }
            }
            __syncthreads();
        }
        if (tid == 0) { top[bh * Uu + it] = sidx[0]; m[sidx[0]] = -1e38f; }
        __syncthreads();
    }
}

// ---------------- attention (verified monolithic version) --------------------
__global__ __launch_bounds__(256) void attn_kernel(const float* __restrict__ Qp,
                                                   const float* __restrict__ Kp,
                                                   const float* __restrict__ Vp,
                                                   const int* __restrict__ top,
                                                   float* __restrict__ attn_out,
                                                   float* __restrict__ ctx)
{
    int b = blockIdx.z, h = blockIdx.y, u = blockIdx.x;
    int tid = threadIdx.x;
    __shared__ float qsh[DK];
    __shared__ float s[Ll];
    __shared__ float red[256];
    __shared__ float part_acc[4][DK];

    int lsel = top[(b * Hh + h) * Uu + u];
    if (tid < DK) qsh[tid] = Qp[((size_t)(b * Ll + lsel) * Hh + h) * DK + tid];
    __syncthreads();

    float q[DK];
#pragma unroll
    for (int d = 0; d < DK; d++) q[d] = qsh[d];

    float lmax = -1e30f;
    for (int k = tid; k < Ll; k += 256) {
        const float* kp = &Kp[((size_t)(b * Ll + k) * Hh + h) * DK];
        float acc = 0.f;
#pragma unroll
        for (int d = 0; d < DK; d += 4) {
            float4 kv = *(const float4*)(kp + d);
            acc += q[d] * kv.x + q[d + 1] * kv.y + q[d + 2] * kv.z + q[d + 3] * kv.w;
        }
        acc *= SCALE;
        s[k] = acc;
        lmax = fmaxf(lmax, acc);
    }
    red[tid] = lmax;
    __syncthreads();
    for (int st = 128; st > 0; st >>= 1) {
        if (tid < st) red[tid] = fmaxf(red[tid], red[tid + st]);
        __syncthreads();
    }
    float mval = red[0];
    __syncthreads();

    float lsum = 0.f;
    for (int k = tid; k < Ll; k += 256) {
        float e = expf(s[k] - mval);
        s[k] = e;
        lsum += e;
    }
    red[tid] = lsum;
    __syncthreads();
    for (int st = 128; st > 0; st >>= 1) {
        if (tid < st) red[tid] += red[tid + st];
        __syncthreads();
    }
    float inv = 1.0f / red[0];
    __syncthreads();

    float* ap = attn_out + ((size_t)((b * Hh + h) * Uu + u)) * Ll;
    for (int k = tid; k < Ll; k += 256) ap[k] = s[k] * inv;

    int d = tid & 63, part = tid >> 6;
    float acc = 0.f;
    for (int k = part; k < Ll; k += 4)
        acc += s[k] * Vp[((size_t)(b * Ll + k) * Hh + h) * DK + d];
    part_acc[part][d] = acc;
    __syncthreads();
    if (part == 0) {
        float t = (part_acc[0][d] + part_acc[1][d] + part_acc[2][d] + part_acc[3][d]) * inv;
        ctx[((size_t)(b * Ll + lsel) * Hh + h) * DK + d] = t;
    }
}

// ---------------- launch ------------------------------------------------------
extern "C" void kernel_launch(void* const* d_in, const int* in_sizes, int n_in,
                              void* d_out, int out_size)
{
    const float* queries = (const float*)d_in[0];
    const float* keys    = (const float*)d_in[1];
    const float* values  = (const float*)d_in[2];
    const int*   sample  = (const int*)d_in[3];
    const float* Wq = (const float*)d_in[4];  const float* bq = (const float*)d_in[5];
    const float* Wk = (const float*)d_in[6];  const float* bk = (const float*)d_in[7];
    const float* Wv = (const float*)d_in[8];  const float* bv = (const float*)d_in[9];
    const float* Wo = (const float*)d_in[10]; const float* bo = (const float*)d_in[11];

    float* out      = (float*)d_out;
    float* attn_out = out + (size_t)MK;

    __nv_bfloat16 *XH, *XL, *X2, *WtH, *WtL, *Wt2, *ctxH, *ctxL;
    float *P, *ctx, *M, *vpart, *vmean;
    int *top;
    cudaGetSymbolAddress((void**)&XH, g_XH);
    cudaGetSymbolAddress((void**)&XL, g_XL);
    cudaGetSymbolAddress((void**)&X2, g_X2);
    cudaGetSymbolAddress((void**)&WtH, g_WtH);
    cudaGetSymbolAddress((void**)&WtL, g_WtL);
    cudaGetSymbolAddress((void**)&Wt2, g_Wt2);
    cudaGetSymbolAddress((void**)&P, g_P);
    cudaGetSymbolAddress((void**)&ctx, g_ctx);
    cudaGetSymbolAddress((void**)&ctxH, g_ctxH);
    cudaGetSymbolAddress((void**)&ctxL, g_ctxL);
    cudaGetSymbolAddress((void**)&M, g_M);
    cudaGetSymbolAddress((void**)&vpart, g_vpart);
    cudaGetSymbolAddress((void**)&vmean, g_vmean);
    cudaGetSymbolAddress((void**)&top, g_top);

    const float* Qp = P;
    const float* Kp = P + MK;
    const float* Vp = P + 2 * (size_t)MK;

    // 1. split inputs into bf16 hi/mid/lo
    conv_split3<<<MK / 1024, 256>>>(queries, XH, XL, X2, MK / 4);
    conv_split3<<<MK / 1024, 256>>>(keys,    XH + MK, XL + MK, X2 + MK, MK / 4);
    conv_split3<<<MK / 1024, 256>>>(values,  XH + 2 * (size_t)MK, XL + 2 * (size_t)MK,
                                    X2 + 2 * (size_t)MK, MK / 4);

    // 2. transpose+split weights (3 levels)
    dim3 wb(32, 8), wg(16, 16);
    conv_w3<<<wg, wb>>>(Wq, WtH + 0 * WSZ, WtL + 0 * WSZ, Wt2 + 0 * WSZ);
    conv_w3<<<wg, wb>>>(Wk, WtH + 1 * WSZ, WtL + 1 * WSZ, Wt2 + 1 * WSZ);
    conv_w3<<<wg, wb>>>(Wv, WtH + 2 * WSZ, WtL + 2 * WSZ, Wt2 + 2 * WSZ);
    conv_w3<<<wg, wb>>>(Wo, WtH + 3 * WSZ, WtL + 3 * WSZ, Wt2 + 3 * WSZ);

    // 3. projections: Q,K = 6-term (selection precision), V = 3-term
    gemm_hmma<<<dim3(128, 4, 3), 256>>>(XH, XL, X2, WtH, WtL, Wt2, bq, bk, bv, P, 0);

    // 4. V mean + ctx broadcast
    vmean1<<<dim3(Hh, Bb, 8), 256>>>(Vp, vpart);
    vmean2<<<32, 64>>>(vpart, vmean);
    fill_ctx<<<(Bb * Ll * Dd) / 256, 256>>>(vmean, ctx);

    // 5. sparse metric + top-k
    metric_kernel<<<dim3(Ll / 256, Hh, Bb), 256>>>(Qp, Kp, sample, M);
    topk_kernel<<<Bb * Hh, 256>>>(M, top);

    // 6. attention
    attn_kernel<<<dim3(Uu, Hh, Bb), 256>>>(Qp, Kp, Vp, top, attn_out, ctx);

    // 7. output GEMM (3-term; X2 region reused as ctx third level scratch)
    conv_split3<<<MK / 1024, 256>>>(ctx, ctxH, ctxL, X2, MK / 4);
    gemm_hmma<<<dim3(128, 4, 1), 256>>>(ctxH, ctxL, X2, WtH + 3 * WSZ, WtL + 3 * WSZ,
                                        Wt2 + 3 * WSZ, bo, bo, bo, out, 1);
}

// round 7
// speedup vs baseline: 1.9137x; 1.5638x over previous
#include <cuda_runtime.h>
#include <cuda_bf16.h>
#include <cstdint>
#include <math.h>

#define Bb 4
#define Ll 4096
#define Dd 512
#define Hh 8
#define DK 64
#define Uu 45
#define UB 5
#define SCALE 0.125f
#define MM 16384
#define MK 8388608
#define WSZ 262144

// ---------------- PTX helpers (plain-sm_103-legal) ---------------------------
__device__ __forceinline__ uint32_t smem_u32(const void* p) {
    uint32_t a;
    asm("{ .reg .u64 t; cvta.to.shared.u64 t, %1; cvt.u32.u64 %0, t; }" : "=r"(a) : "l"(p));
    return a;
}
#define CP_ASYNC16(dst, src) \
    asm volatile("cp.async.cg.shared.global [%0], [%1], 16;" :: "r"(dst), "l"(src))
#define CP_COMMIT() asm volatile("cp.async.commit_group;" ::: "memory")
#define CP_WAIT1()  asm volatile("cp.async.wait_group 1;" ::: "memory")

__device__ __forceinline__ void ldsm_x4(uint32_t* r, uint32_t addr) {
    asm volatile("ldmatrix.sync.aligned.m8n8.x4.shared.b16 {%0,%1,%2,%3}, [%4];"
        : "=r"(r[0]), "=r"(r[1]), "=r"(r[2]), "=r"(r[3]) : "r"(addr));
}
__device__ __forceinline__ void mma_bf16(float* d, const uint32_t* a, uint32_t b0, uint32_t b1) {
    asm volatile("mma.sync.aligned.m16n8k16.row.col.f32.bf16.bf16.f32 "
        "{%0,%1,%2,%3}, {%4,%5,%6,%7}, {%8,%9}, {%0,%1,%2,%3};"
        : "+f"(d[0]), "+f"(d[1]), "+f"(d[2]), "+f"(d[3])
        : "r"(a[0]), "r"(a[1]), "r"(a[2]), "r"(a[3]), "r"(b0), "r"(b1));
}

// ---------------- scratch ----------------------------------------------------
__device__ __nv_bfloat16 g_XH[3 * MK];
__device__ __nv_bfloat16 g_XL[3 * MK];
__device__ __nv_bfloat16 g_X2[3 * MK];
__device__ __nv_bfloat16 g_WtH[4 * WSZ];
__device__ __nv_bfloat16 g_WtL[4 * WSZ];
__device__ __nv_bfloat16 g_Wt2[4 * WSZ];
__device__ float g_P[3 * MK];              // Qp | Kp | Vp, (B,L,H,dk)
__device__ float g_ctx[MK];
__device__ __nv_bfloat16 g_ctxH[MK];
__device__ __nv_bfloat16 g_ctxL[MK];
__device__ float g_M[Bb * Hh * Ll];
__device__ float g_vpart[32 * 8 * 64];
__device__ float g_vmean[Bb * Dd];
__device__ int   g_top[Bb * Hh * Uu];

// ---------------- 3-level split conversion -----------------------------------
__global__ __launch_bounds__(256) void conv_split3(const float* __restrict__ x,
                                                   __nv_bfloat16* __restrict__ h,
                                                   __nv_bfloat16* __restrict__ m,
                                                   __nv_bfloat16* __restrict__ l, int n4)
{
    int i = blockIdx.x * 256 + threadIdx.x;
    if (i >= n4) return;
    float4 v = ((const float4*)x)[i];
    float vv[4] = {v.x, v.y, v.z, v.w};
    __nv_bfloat16 hh[4], mm[4], ll[4];
#pragma unroll
    for (int j = 0; j < 4; j++) {
        hh[j] = __float2bfloat16(vv[j]);
        float r1 = vv[j] - __bfloat162float(hh[j]);
        mm[j] = __float2bfloat16(r1);
        ll[j] = __float2bfloat16(r1 - __bfloat162float(mm[j]));
    }
    ((__nv_bfloat162*)h)[2 * i + 0] = __halves2bfloat162(hh[0], hh[1]);
    ((__nv_bfloat162*)h)[2 * i + 1] = __halves2bfloat162(hh[2], hh[3]);
    ((__nv_bfloat162*)m)[2 * i + 0] = __halves2bfloat162(mm[0], mm[1]);
    ((__nv_bfloat162*)m)[2 * i + 1] = __halves2bfloat162(mm[2], mm[3]);
    ((__nv_bfloat162*)l)[2 * i + 0] = __halves2bfloat162(ll[0], ll[1]);
    ((__nv_bfloat162*)l)[2 * i + 1] = __halves2bfloat162(ll[2], ll[3]);
}

__global__ void conv_w3(const float* __restrict__ W,
                        __nv_bfloat16* __restrict__ WtH,
                        __nv_bfloat16* __restrict__ WtL,
                        __nv_bfloat16* __restrict__ Wt2)
{
    __shared__ float t[32][33];
    int n0 = blockIdx.x * 32, k0 = blockIdx.y * 32;
    int tx = threadIdx.x, ty = threadIdx.y;
#pragma unroll
    for (int i = 0; i < 4; i++)
        t[ty + i * 8][tx] = W[(size_t)(k0 + ty + i * 8) * 512 + n0 + tx];
    __syncthreads();
#pragma unroll
    for (int i = 0; i < 4; i++) {
        int n = n0 + ty + i * 8;
        float v = t[tx][ty + i * 8];
        __nv_bfloat16 hb = __float2bfloat16(v);
        float r1 = v - __bfloat162float(hb);
        __nv_bfloat16 mb = __float2bfloat16(r1);
        WtH[(size_t)n * 512 + k0 + tx] = hb;
        WtL[(size_t)n * 512 + k0 + tx] = mb;
        Wt2[(size_t)n * 512 + k0 + tx] = __float2bfloat16(r1 - __bfloat162float(mb));
    }
}

// ---------------- bf16 HMMA GEMM, 3-stage cp.async, 1 sync/chunk -------------
__device__ __constant__ int c_tA[6] = {0, 0, 1, 0, 2, 1};
__device__ __constant__ int c_tB[6] = {0, 1, 0, 2, 0, 1};
#define LDAB 40
#define STG_BYTES (128 * LDAB * 2)          // 10240 per operand per stage
#define GEMM_SMEM (3 * 2 * STG_BYTES)       // 61440

__global__ __launch_bounds__(256, 2) void gemm_hmma(
    const __nv_bfloat16* __restrict__ A0, const __nv_bfloat16* __restrict__ A1,
    const __nv_bfloat16* __restrict__ A2,
    const __nv_bfloat16* __restrict__ B0, const __nv_bfloat16* __restrict__ B1,
    const __nv_bfloat16* __restrict__ B2,
    const float* __restrict__ bi0, const float* __restrict__ bi1, const float* __restrict__ bi2,
    float* __restrict__ Cout, int mode)
{
    extern __shared__ char sm[];
    const int tid = threadIdx.x;
    const int w = tid >> 5, lane = tid & 31;
    const int z = blockIdx.z;
    const int m0 = blockIdx.x * 128, n0 = blockIdx.y * 128;
    const int nt = mode ? 3 : (z == 2 ? 3 : 6);
    const int NCH = nt * 16;

    const __nv_bfloat16* Alev[3] = {A0 + (size_t)z * MK, A1 + (size_t)z * MK, A2 + (size_t)z * MK};
    const __nv_bfloat16* Blev[3] = {B0 + (size_t)z * WSZ, B1 + (size_t)z * WSZ, B2 + (size_t)z * WSZ};

    const int m_off = (w >> 2) * 64, n_off = (w & 3) * 32;
    const int mi = lane >> 3, r8 = lane & 7;

    float acc[4][4][4];
#pragma unroll
    for (int i = 0; i < 4; i++)
#pragma unroll
        for (int j = 0; j < 4; j++)
#pragma unroll
            for (int q = 0; q < 4; q++) acc[i][j][q] = 0.f;

    const uint32_t sbase = smem_u32(sm);
    const int lrow = tid >> 2;
    const int lcg  = (tid & 3) * 8;

    auto load_chunk = [&](int c, int stg) {
        int t = c >> 4, k0 = (c & 15) * 32;
        const __nv_bfloat16* Asrc = Alev[c_tA[t]];
        const __nv_bfloat16* Bsrc = Blev[c_tB[t]];
        uint32_t sA = sbase + stg * (2 * STG_BYTES);
        uint32_t sB = sA + STG_BYTES;
#pragma unroll
        for (int i = 0; i < 2; i++) {
            int row = lrow + i * 64;
            CP_ASYNC16(sA + (row * LDAB + lcg) * 2, Asrc + (size_t)(m0 + row) * 512 + k0 + lcg);
            CP_ASYNC16(sB + (row * LDAB + lcg) * 2, Bsrc + (size_t)(n0 + row) * 512 + k0 + lcg);
        }
    };

    load_chunk(0, 0); CP_COMMIT();
    load_chunk(1, 1); CP_COMMIT();

    int buf = 0, pre = 2;                 // pre = stage for chunk c+2
    for (int c = 0; c < NCH; c++) {
        CP_WAIT1();
        __syncthreads();
        if (c + 2 < NCH) load_chunk(c + 2, pre);
        CP_COMMIT();

        uint32_t sA = sbase + buf * (2 * STG_BYTES);
        uint32_t sB = sA + STG_BYTES;
#pragma unroll
        for (int kk = 0; kk < 2; kk++) {
            uint32_t a[4][4], b[2][4];
#pragma unroll
            for (int i = 0; i < 4; i++)
                ldsm_x4(a[i], sA + (uint32_t)(m_off + i * 16 + ((mi & 1) << 3) + r8) * 80
                              + kk * 32 + ((mi >> 1) << 4));
#pragma unroll
            for (int jg = 0; jg < 2; jg++)
                ldsm_x4(b[jg], sB + (uint32_t)(n_off + jg * 16 + ((mi >> 1) << 3) + r8) * 80
                               + kk * 32 + ((mi & 1) << 4));
#pragma unroll
            for (int i = 0; i < 4; i++)
#pragma unroll
                for (int j = 0; j < 4; j++)
                    mma_bf16(acc[i][j], a[i], b[j >> 1][(j & 1) * 2], b[j >> 1][(j & 1) * 2 + 1]);
        }
        buf = (buf == 2) ? 0 : buf + 1;
        pre = (pre == 2) ? 0 : pre + 1;
    }

    const float* bs = (z == 0) ? bi0 : (z == 1) ? bi1 : bi2;
    float* Cz = Cout + (size_t)z * MK;
#pragma unroll
    for (int i = 0; i < 4; i++) {
        int row0 = m0 + m_off + i * 16 + (lane >> 2);
#pragma unroll
        for (int j = 0; j < 4; j++) {
            int col = n0 + n_off + j * 8 + (lane & 3) * 2;
            float bx = bs[col], by = bs[col + 1];
            float2 v0 = make_float2(acc[i][j][0] + bx, acc[i][j][1] + by);
            float2 v1 = make_float2(acc[i][j][2] + bx, acc[i][j][3] + by);
            *(float2*)(Cz + (size_t)row0 * 512 + col) = v0;
            *(float2*)(Cz + (size_t)(row0 + 8) * 512 + col) = v1;
        }
    }
}

// ---------------- V mean (two-stage) ----------------------------------------
__global__ __launch_bounds__(256) void vmean1(const float* __restrict__ Vp, float* __restrict__ vpart)
{
    int h = blockIdx.x, b = blockIdx.y, p = blockIdx.z;
    int d = threadIdx.x & 63, sub = threadIdx.x >> 6;
    float s = 0.f;
    for (int k = p * 512 + sub; k < (p + 1) * 512; k += 4)
        s += Vp[((size_t)(b * Ll + k) * Hh + h) * DK + d];
    __shared__ float smm[4][64];
    smm[sub][d] = s;
    __syncthreads();
    if (sub == 0)
        vpart[((size_t)((b * Hh + h) * 8 + p)) * 64 + d] = smm[0][d] + smm[1][d] + smm[2][d] + smm[3][d];
}

__global__ void vmean2(const float* __restrict__ vpart, float* __restrict__ vmean)
{
    int bh = blockIdx.x, d = threadIdx.x;
    float s = 0.f;
    for (int p = 0; p < 8; p++) s += vpart[(bh * 8 + p) * 64 + d];
    vmean[(bh >> 3) * Dd + (bh & 7) * DK + d] = s * (1.0f / Ll);
}

__global__ __launch_bounds__(256) void fill_ctx(const float* __restrict__ vmean, float* __restrict__ ctx)
{
    int i = blockIdx.x * 256 + threadIdx.x;            // float4 index
    int b4 = i / (Ll * Dd / 4);
    int c4 = i % (Dd / 4);
    ((float4*)ctx)[i] = ((const float4*)vmean)[b4 * (Dd / 4) + c4];
}

// ---------------- sparse metric (d-tiled, LDS:FMA = 0.25) --------------------
__global__ __launch_bounds__(256) void metric_kernel(const float* __restrict__ Qp,
                                                     const float* __restrict__ Kp,
                                                     const int* __restrict__ sample_idx,
                                                     float* __restrict__ Mout)
{
    int b = blockIdx.z, h = blockIdx.y;
    int l = blockIdx.x * 256 + threadIdx.x;
    __shared__ float Ks[Uu * DK];
    for (int i = threadIdx.x; i < Uu * DK; i += 256) {
        int j = i / DK, d = i % DK;
        int ksl = sample_idx[j];
        Ks[i] = Kp[((size_t)(b * Ll + ksl) * Hh + h) * DK + d];
    }
    __syncthreads();
    const float* qp = &Qp[((size_t)(b * Ll + l) * Hh + h) * DK];
    float acc[Uu];
#pragma unroll
    for (int u = 0; u < Uu; u++) acc[u] = 0.f;
    for (int d0 = 0; d0 < DK; d0 += 8) {
        float4 a0 = *(const float4*)(qp + d0);
        float4 a1 = *(const float4*)(qp + d0 + 4);
#pragma unroll
        for (int u = 0; u < Uu; u++) {
            float4 b0 = *(const float4*)&Ks[u * DK + d0];
            float4 b1 = *(const float4*)&Ks[u * DK + d0 + 4];
            acc[u] += a0.x * b0.x + a0.y * b0.y + a0.z * b0.z + a0.w * b0.w
                    + a1.x * b1.x + a1.y * b1.y + a1.z * b1.z + a1.w * b1.w;
        }
    }
    float mx = -1e30f, sum = 0.f;
#pragma unroll
    for (int u = 0; u < Uu; u++) { mx = fmaxf(mx, acc[u]); sum += acc[u]; }
    Mout[(b * Hh + h) * Ll + l] = mx - sum * (1.0f / Uu);
}

// ---------------- top-45 ------------------------------------------------------
__global__ __launch_bounds__(256) void topk_kernel(const float* __restrict__ Min, int* __restrict__ top)
{
    int bh = blockIdx.x;
    int tid = threadIdx.x;
    __shared__ float m[Ll];
    __shared__ float sval[256];
    __shared__ int   sidx[256];
    for (int k = tid; k < Ll; k += 256) m[k] = Min[bh * Ll + k];
    __syncthreads();
    for (int it = 0; it < Uu; it++) {
        float bv = -1e38f; int bi = Ll;
        for (int k = tid; k < Ll; k += 256) {
            float v = m[k];
            if (v > bv) { bv = v; bi = k; }
        }
        sval[tid] = bv; sidx[tid] = bi;
        __syncthreads();
        for (int s = 128; s > 0; s >>= 1) {
            if (tid < s) {
                float v2 = sval[tid + s]; int i2 = sidx[tid + s];
                if (v2 > sval[tid] || (v2 == sval[tid] && i2 < sidx[tid])) {
                    sval[tid] = v2; sidx[tid] = i2;
                }
            }
            __syncthreads();
        }
        if (tid == 0) { top[bh * Uu + it] = sidx[0]; m[sidx[0]] = -1e38f; }
        __syncthreads();
    }
}

// ---------------- attention: 5 queries per block ------------------------------
// dyn smem: s[5][4096] | qsh[5*64] | red[5*256] | pacc[4][5][64]
#define ATTN_SMEM ((UB * Ll + UB * DK + UB * 256 + 4 * UB * DK) * 4)

__global__ __launch_bounds__(256) void attn5_kernel(const float* __restrict__ Qp,
                                                    const float* __restrict__ Kp,
                                                    const float* __restrict__ Vp,
                                                    const int* __restrict__ top,
                                                    float* __restrict__ attn_out,
                                                    float* __restrict__ ctx)
{
    extern __shared__ float dsm[];
    float* s    = dsm;                    // UB*4096
    float* qsh  = s + UB * Ll;            // UB*64
    float* red  = qsh + UB * DK;          // UB*256
    float* pacc = red + UB * 256;         // 4*UB*64

    int b = blockIdx.z, h = blockIdx.y, u0 = blockIdx.x * UB;
    int bh = b * Hh + h;
    int tid = threadIdx.x;

    for (int i = tid; i < UB * DK; i += 256) {
        int u = i >> 6, d = i & 63;
        int lsel = top[bh * Uu + u0 + u];
        qsh[i] = Qp[((size_t)(b * Ll + lsel) * Hh + h) * DK + d];
    }
    __syncthreads();

    // scores + per-thread max
    float mx[UB];
#pragma unroll
    for (int u = 0; u < UB; u++) mx[u] = -1e30f;
    for (int k = tid; k < Ll; k += 256) {
        const float* kp = &Kp[((size_t)(b * Ll + k) * Hh + h) * DK];
        float acc[UB];
#pragma unroll
        for (int u = 0; u < UB; u++) acc[u] = 0.f;
#pragma unroll
        for (int d0 = 0; d0 < DK; d0 += 8) {
            float4 k0 = *(const float4*)(kp + d0);
            float4 k1 = *(const float4*)(kp + d0 + 4);
#pragma unroll
            for (int u = 0; u < UB; u++) {
                float4 q0 = *(const float4*)&qsh[u * DK + d0];
                float4 q1 = *(const float4*)&qsh[u * DK + d0 + 4];
                acc[u] += k0.x * q0.x + k0.y * q0.y + k0.z * q0.z + k0.w * q0.w
                        + k1.x * q1.x + k1.y * q1.y + k1.z * q1.z + k1.w * q1.w;
            }
        }
#pragma unroll
        for (int u = 0; u < UB; u++) {
            float v = acc[u] * SCALE;
            s[u * Ll + k] = v;
            mx[u] = fmaxf(mx[u], v);
        }
    }
#pragma unroll
    for (int u = 0; u < UB; u++) red[u * 256 + tid] = mx[u];
    __syncthreads();
    for (int st = 128; st > 0; st >>= 1) {
        if (tid < st)
#pragma unroll
            for (int u = 0; u < UB; u++)
                red[u * 256 + tid] = fmaxf(red[u * 256 + tid], red[u * 256 + tid + st]);
        __syncthreads();
    }
    float mval[UB];
#pragma unroll
    for (int u = 0; u < UB; u++) mval[u] = red[u * 256];
    __syncthreads();

    // exp + per-thread sum
    float sums[UB];
#pragma unroll
    for (int u = 0; u < UB; u++) sums[u] = 0.f;
    for (int k = tid; k < Ll; k += 256) {
#pragma unroll
        for (int u = 0; u < UB; u++) {
            float e = expf(s[u * Ll + k] - mval[u]);
            s[u * Ll + k] = e;
            sums[u] += e;
        }
    }
#pragma unroll
    for (int u = 0; u < UB; u++) red[u * 256 + tid] = sums[u];
    __syncthreads();
    for (int st = 128; st > 0; st >>= 1) {
        if (tid < st)
#pragma unroll
            for (int u = 0; u < UB; u++)
                red[u * 256 + tid] += red[u * 256 + tid + st];
        __syncthreads();
    }
    float inv[UB];
#pragma unroll
    for (int u = 0; u < UB; u++) inv[u] = 1.0f / red[u * 256];

    // write normalized attn rows
#pragma unroll
    for (int u = 0; u < UB; u++) {
        float* ap = attn_out + ((size_t)(bh * Uu + u0 + u)) * Ll;
        for (int k = tid; k < Ll; k += 256) ap[k] = s[u * Ll + k] * inv[u];
    }

    // AV: thread p=tid>>6 owns k-range, d=tid&63
    int d = tid & 63, p = tid >> 6;
    float acc[UB];
#pragma unroll
    for (int u = 0; u < UB; u++) acc[u] = 0.f;
    int kbeg = p * (Ll / 4), kend = kbeg + (Ll / 4);
    for (int k0 = kbeg; k0 < kend; k0 += 4) {
        float4 sv[UB];
#pragma unroll
        for (int u = 0; u < UB; u++) sv[u] = *(const float4*)&s[u * Ll + k0];
#pragma unroll
        for (int j = 0; j < 4; j++) {
            float v = Vp[((size_t)(b * Ll + k0 + j) * Hh + h) * DK + d];
#pragma unroll
            for (int u = 0; u < UB; u++) {
                float sj = (j == 0) ? sv[u].x : (j == 1) ? sv[u].y : (j == 2) ? sv[u].z : sv[u].w;
                acc[u] += sj * v;
            }
        }
    }
#pragma unroll
    for (int u = 0; u < UB; u++) pacc[(p * UB + u) * DK + d] = acc[u];
    __syncthreads();
    for (int i = tid; i < UB * DK; i += 256) {
        int u = i >> 6, dd = i & 63;
        float t = (pacc[(0 * UB + u) * DK + dd] + pacc[(1 * UB + u) * DK + dd]
                 + pacc[(2 * UB + u) * DK + dd] + pacc[(3 * UB + u) * DK + dd]) * inv[u];
        int lsel = top[bh * Uu + u0 + u];
        ctx[((size_t)(b * Ll + lsel) * Hh + h) * DK + dd] = t;
    }
}

// ---------------- launch ------------------------------------------------------
extern "C" void kernel_launch(void* const* d_in, const int* in_sizes, int n_in,
                              void* d_out, int out_size)
{
    const float* queries = (const float*)d_in[0];
    const float* keys    = (const float*)d_in[1];
    const float* values  = (const float*)d_in[2];
    const int*   sample  = (const int*)d_in[3];
    const float* Wq = (const float*)d_in[4];  const float* bq = (const float*)d_in[5];
    const float* Wk = (const float*)d_in[6];  const float* bk = (const float*)d_in[7];
    const float* Wv = (const float*)d_in[8];  const float* bv = (const float*)d_in[9];
    const float* Wo = (const float*)d_in[10]; const float* bo = (const float*)d_in[11];

    float* out      = (float*)d_out;
    float* attn_out = out + (size_t)MK;

    __nv_bfloat16 *XH, *XL, *X2, *WtH, *WtL, *Wt2, *ctxH, *ctxL;
    float *P, *ctx, *M, *vpart, *vmean;
    int *top;
    cudaGetSymbolAddress((void**)&XH, g_XH);
    cudaGetSymbolAddress((void**)&XL, g_XL);
    cudaGetSymbolAddress((void**)&X2, g_X2);
    cudaGetSymbolAddress((void**)&WtH, g_WtH);
    cudaGetSymbolAddress((void**)&WtL, g_WtL);
    cudaGetSymbolAddress((void**)&Wt2, g_Wt2);
    cudaGetSymbolAddress((void**)&P, g_P);
    cudaGetSymbolAddress((void**)&ctx, g_ctx);
    cudaGetSymbolAddress((void**)&ctxH, g_ctxH);
    cudaGetSymbolAddress((void**)&ctxL, g_ctxL);
    cudaGetSymbolAddress((void**)&M, g_M);
    cudaGetSymbolAddress((void**)&vpart, g_vpart);
    cudaGetSymbolAddress((void**)&vmean, g_vmean);
    cudaGetSymbolAddress((void**)&top, g_top);

    cudaFuncSetAttribute(gemm_hmma, cudaFuncAttributeMaxDynamicSharedMemorySize, GEMM_SMEM);
    cudaFuncSetAttribute(attn5_kernel, cudaFuncAttributeMaxDynamicSharedMemorySize, ATTN_SMEM);

    const float* Qp = P;
    const float* Kp = P + MK;
    const float* Vp = P + 2 * (size_t)MK;

    // 1. split inputs into bf16 hi/mid/lo
    conv_split3<<<MK / 1024, 256>>>(queries, XH, XL, X2, MK / 4);
    conv_split3<<<MK / 1024, 256>>>(keys,    XH + MK, XL + MK, X2 + MK, MK / 4);
    conv_split3<<<MK / 1024, 256>>>(values,  XH + 2 * (size_t)MK, XL + 2 * (size_t)MK,
                                    X2 + 2 * (size_t)MK, MK / 4);

    // 2. transpose+split weights
    dim3 wb(32, 8), wg(16, 16);
    conv_w3<<<wg, wb>>>(Wq, WtH + 0 * WSZ, WtL + 0 * WSZ, Wt2 + 0 * WSZ);
    conv_w3<<<wg, wb>>>(Wk, WtH + 1 * WSZ, WtL + 1 * WSZ, Wt2 + 1 * WSZ);
    conv_w3<<<wg, wb>>>(Wv, WtH + 2 * WSZ, WtL + 2 * WSZ, Wt2 + 2 * WSZ);
    conv_w3<<<wg, wb>>>(Wo, WtH + 3 * WSZ, WtL + 3 * WSZ, Wt2 + 3 * WSZ);

    // 3. projections: Q,K = 6-term, V = 3-term
    gemm_hmma<<<dim3(128, 4, 3), 256, GEMM_SMEM>>>(XH, XL, X2, WtH, WtL, Wt2, bq, bk, bv, P, 0);

    // 4. V mean + ctx broadcast
    vmean1<<<dim3(Hh, Bb, 8), 256>>>(Vp, vpart);
    vmean2<<<32, 64>>>(vpart, vmean);
    fill_ctx<<<(MK / 4) / 256, 256>>>(vmean, ctx);

    // 5. sparse metric + top-k
    metric_kernel<<<dim3(Ll / 256, Hh, Bb), 256>>>(Qp, Kp, sample, M);
    topk_kernel<<<Bb * Hh, 256>>>(M, top);

    // 6. attention (5 queries per block)
    attn5_kernel<<<dim3(Uu / UB, Hh, Bb), 256, ATTN_SMEM>>>(Qp, Kp, Vp, top, attn_out, ctx);

    // 7. output GEMM (3-term)
    conv_split3<<<MK / 1024, 256>>>(ctx, ctxH, ctxL, X2, MK / 4);
    gemm_hmma<<<dim3(128, 4, 1), 256, GEMM_SMEM>>>(ctxH, ctxL, X2, WtH + 3 * WSZ, WtL + 3 * WSZ,
                                                   Wt2 + 3 * WSZ, bo, bo, bo, out, 1);
}